// round 16
// baseline (speedup 1.0000x reference)
#include <cuda_runtime.h>
#include <cuda_bf16.h>
#include <cuda_fp16.h>
#include <math.h>
#include <cstdint>

// ---------------------------------------------------------------------------
// SOMI settling layer — Paterson-Stockmeyer collapsed formulation.
//   N = |W|/deg - (1.1 + p) on diag;  H = (1-g)I + g*(D0 + N^4(D1 + N^4 D2))
//   out = H @ h over the hidden dim.
// Poly chain: mma.sync bf16 hi/lo 3-product, 32x64 CTA, 8 warps with
// warp-level split-K (two k-halves, smem combine) — R15's 4-warp version had
// 1 warp/SMSP and 8 serial chunks, fully latency-exposed.
// Big GEMM: mma.sync fp16 single-product, 128x64 CTA, 2 CTAs/SM (near floor).
//
// HARD RULES LEARNED:
//  R3/R4: never pass __device__ global symbols as host-side kernel args.
//  R6:    harness compiles baseline sm_100 -> no tcgen05/TMEM; mma.sync only.
//  R9:    single-buffered smem mma loops are ~90% stalled -> cp.async pipeline.
//  R11:   big GEMM hit the mma.sync compute floor -> fp16 single product.
//  R13:   16-chunk loops are barrier/ldmatrix latency-bound -> BK=64.
//  R14:   2 accumulators/warp -> MMA RAW chain bound -> 4 accs.
//  R15:   1 warp/SMSP exposes all latency -> warp split-K for 2 warps/SMSP.
// ---------------------------------------------------------------------------

#define DIM 512
#define RMAX (4 * 4096)

// fp32 arena ids
#define BUF_N   0
#define BUF_N2  1
#define BUF_N3  2
#define BUF_D0  3
#define BUF_D1  4
// bf16 hi/lo arena ids
#define HB_N    0
#define HB_N2   1
#define HB_N4   2
#define HB_D2   3
#define HB_E    4

__device__ __align__(16) float g_buf[5][DIM * DIM];
__device__ __align__(16) __nv_bfloat16 g_bhi[5][DIM * DIM];
__device__ __align__(16) __nv_bfloat16 g_blo[5][DIM * DIM];
__device__ __align__(16) __half g_Hf[DIM * DIM];      // H in fp16 (big GEMM B)
__device__ __align__(16) __half g_hf[RMAX * DIM];     // h in fp16 (big GEMM A)

struct Coef { float P[3][4]; float Q[3][4]; };
struct Job  { int ahl, bhl, mode, addi, outfp, outhl, outf16; };

// ======================= helpers ===========================================
__device__ __forceinline__ uint32_t smem_u32(const void* p) {
    uint32_t a;
    asm("{ .reg .u64 t; cvta.to.shared.u64 t, %1; cvt.u32.u64 %0, t; }"
        : "=r"(a) : "l"(p));
    return a;
}
__device__ __forceinline__ uint32_t bf2_pack(__nv_bfloat16 a, __nv_bfloat16 b) {
    __nv_bfloat162 t = __halves2bfloat162(a, b);
    return *reinterpret_cast<uint32_t*>(&t);
}
__device__ __forceinline__ void cp16(uint32_t dst, const void* src) {
    asm volatile("cp.async.cg.shared.global [%0], [%1], 16;"
                 :: "r"(dst), "l"(src) : "memory");
}
#define CP_COMMIT() asm volatile("cp.async.commit_group;" ::: "memory")
#define CP_WAIT1()  asm volatile("cp.async.wait_group 1;" ::: "memory")
#define CP_WAIT0()  asm volatile("cp.async.wait_group 0;" ::: "memory")

__device__ __forceinline__ void ldm_x4(uint32_t& r0, uint32_t& r1,
                                       uint32_t& r2, uint32_t& r3, uint32_t a) {
    asm volatile("ldmatrix.sync.aligned.m8n8.x4.shared.b16 {%0,%1,%2,%3}, [%4];"
                 : "=r"(r0), "=r"(r1), "=r"(r2), "=r"(r3) : "r"(a));
}
__device__ __forceinline__ void ldm_x2(uint32_t& r0, uint32_t& r1, uint32_t a) {
    asm volatile("ldmatrix.sync.aligned.m8n8.x2.shared.b16 {%0,%1}, [%2];"
                 : "=r"(r0), "=r"(r1) : "r"(a));
}
__device__ __forceinline__ void ldm_x4t(uint32_t& r0, uint32_t& r1,
                                        uint32_t& r2, uint32_t& r3, uint32_t a) {
    asm volatile("ldmatrix.sync.aligned.m8n8.x4.trans.shared.b16 {%0,%1,%2,%3}, [%4];"
                 : "=r"(r0), "=r"(r1), "=r"(r2), "=r"(r3) : "r"(a));
}
__device__ __forceinline__ void mma_bf16(float* c, const uint32_t* a,
                                         const uint32_t* b) {
    asm volatile(
        "mma.sync.aligned.m16n8k16.row.col.f32.bf16.bf16.f32 "
        "{%0,%1,%2,%3}, {%4,%5,%6,%7}, {%8,%9}, {%0,%1,%2,%3};"
        : "+f"(c[0]), "+f"(c[1]), "+f"(c[2]), "+f"(c[3])
        : "r"(a[0]), "r"(a[1]), "r"(a[2]), "r"(a[3]), "r"(b[0]), "r"(b[1]));
}
__device__ __forceinline__ void mma_f16(float* c, const uint32_t* a,
                                        const uint32_t* b) {
    asm volatile(
        "mma.sync.aligned.m16n8k16.row.col.f32.f16.f16.f32 "
        "{%0,%1,%2,%3}, {%4,%5,%6,%7}, {%8,%9}, {%0,%1,%2,%3};"
        : "+f"(c[0]), "+f"(c[1]), "+f"(c[2]), "+f"(c[3])
        : "r"(a[0]), "r"(a[1]), "r"(a[2]), "r"(a[3]), "r"(b[0]), "r"(b[1]));
}
__device__ __forceinline__ void split_store(int hl, int off, float v0, float v1) {
    __nv_bfloat16 h0 = __float2bfloat16_rn(v0);
    __nv_bfloat16 h1 = __float2bfloat16_rn(v1);
    __nv_bfloat16 l0 = __float2bfloat16_rn(v0 - __bfloat162float(h0));
    __nv_bfloat16 l1 = __float2bfloat16_rn(v1 - __bfloat162float(h1));
    *(uint32_t*)&g_bhi[hl][off] = bf2_pack(h0, h1);
    *(uint32_t*)&g_blo[hl][off] = bf2_pack(l0, l1);
}

// ======================= build kernels =====================================
__global__ __launch_bounds__(256)
void build_degN(const float* __restrict__ W, const float* __restrict__ p) {
    __shared__ float red[8];
    const int e   = blockIdx.x;
    const int tid = threadIdx.x;
    const float* row = W + (size_t)e * DIM;

    float s = fabsf(row[tid]) + fabsf(row[tid + 256]);
    #pragma unroll
    for (int o = 16; o > 0; o >>= 1) s += __shfl_down_sync(0xffffffffu, s, o);
    if ((tid & 31) == 0) red[tid >> 5] = s;
    __syncthreads();
    if (tid == 0) {
        float t = 0.f;
        #pragma unroll
        for (int w = 0; w < 8; w++) t += red[w];
        red[0] = fmaxf(t, 1e-8f);
    }
    __syncthreads();
    const float dg = red[0];

    int d = tid * 2;
    int idx = e * DIM + d;
    float m0 = fabsf(row[d])     / dg;
    float m1 = fabsf(row[d + 1]) / dg;
    if (e == d)     m0 -= (1.1f + p[d]);
    if (e == d + 1) m1 -= (1.1f + p[d + 1]);
    g_buf[BUF_N][idx]     = m0;
    g_buf[BUF_N][idx + 1] = m1;
    split_store(HB_N, idx, m0, m1);
}

__global__ void split_h(const float* __restrict__ h, int nvec) {
    int v = blockIdx.x * blockDim.x + threadIdx.x;
    if (v >= nvec) return;
    float4 x = ((const float4*)h)[v];
    int idx = v * 4;
    __half2 a = __floats2half2_rn(x.x, x.y);
    __half2 b = __floats2half2_rn(x.z, x.w);
    *(uint2*)&g_hf[idx] = make_uint2(*(uint32_t*)&a, *(uint32_t*)&b);
}

__global__ __launch_bounds__(256)
void build_D(const float* __restrict__ p, Coef cf) {
    int v = blockIdx.x * blockDim.x + threadIdx.x;
    if (v >= DIM * DIM / 2) return;
    int idx = v * 2;
    int e = idx >> 9;
    int d = idx & (DIM - 1);
    float r[3][2];
    #pragma unroll
    for (int u = 0; u < 2; u++) {
        int dd = d + u;
        float x0 = (e == dd) ? 1.f : 0.f;
        float x1 = g_buf[BUF_N ][idx + u];
        float x2 = g_buf[BUF_N2][idx + u];
        float x3 = g_buf[BUF_N3][idx + u];
        float pd = p[dd];
        #pragma unroll
        for (int j = 0; j < 3; j++) {
            float vp = cf.P[j][0] * x0 + cf.P[j][1] * x1 + cf.P[j][2] * x2 + cf.P[j][3] * x3;
            float vq = cf.Q[j][0] * x0 + cf.Q[j][1] * x1 + cf.Q[j][2] * x2 + cf.Q[j][3] * x3;
            r[j][u] = vp + vq * pd;
        }
    }
    g_buf[BUF_D0][idx]     = r[0][0];
    g_buf[BUF_D0][idx + 1] = r[0][1];
    g_buf[BUF_D1][idx]     = r[1][0];
    g_buf[BUF_D1][idx + 1] = r[1][1];
    split_store(HB_D2, idx, r[2][0], r[2][1]);
}

// ======================= mma.sync 512^3 GEMM (warp split-K) ================
// C = A(hi/lo) @ B(hi/lo); CTA 32x64, grid (16,8,z), 256 threads / 8 warps.
// kg = wid>>2 selects k-half [kg*256, kg*256+256); wc = wid&3 selects the
// 16-col quarter. Each warp: 4 chunks of BK=64, 4 independent accumulators.
// Halves combined via 8KB smem reduction; epilogue on kg=0 warps.
// Smem: 4 chunk blocks (2 halves x 2 stages), 27648 B each = 110592 B.
//   block(g,s) = g*55296 + s*27648; within: AHI@0 ALO@4608 BHI@9216 BLO@18432
#define M5_CHK  27648
#define M5_HALF 55296
#define M5_ALO  4608
#define M5_BHI  9216
#define M5_BLO  18432
#define M5_TOT  110592
#define KPAD 72

__global__ __launch_bounds__(256, 1)
void mma512(Job j0, Job j1, const float* __restrict__ ga) {
    extern __shared__ char dsm[];
    const uint32_t sb = smem_u32(dsm);

    const Job j = (blockIdx.z == 0) ? j0 : j1;
    const int tid  = threadIdx.x;
    const int wid  = tid >> 5;
    const int lane = tid & 31;
    const int kg   = wid >> 2;        // k-half
    const int wc   = wid & 3;         // n quarter (16 cols)
    const int brow = blockIdx.x * 32;
    const int bcol = blockIdx.y * 64;

    const __nv_bfloat16* __restrict__ Ah = g_bhi[j.ahl];
    const __nv_bfloat16* __restrict__ Al = g_blo[j.ahl];
    const __nv_bfloat16* __restrict__ Bh = g_bhi[j.bhl];
    const __nv_bfloat16* __restrict__ Bl = g_blo[j.bhl];

    float acc[2][2][4];
    #pragma unroll
    for (int mt = 0; mt < 2; mt++)
        #pragma unroll
        for (int nt = 0; nt < 2; nt++)
            #pragma unroll
            for (int q = 0; q < 4; q++) acc[mt][nt][q] = 0.f;

    const int aRowL = lane & 15;
    const int aKp   = (lane >> 4) * 8;
    const int bg    = lane >> 3;
    const int bro   = (bg & 1) * 8 + (lane & 7);
    const int bco   = wc * 16 + (bg >> 1) * 8;

    // loader lanes (256 threads): A 32x8 = 256 slots (1 hi + 1 lo each);
    // B 64x8 = 512 slots (2 hi + 2 lo each)
    const int lar = tid >> 3, laq = tid & 7;

    // chunk loader: half g, stage s, global k
    #define LOAD_CHUNK(g, s, k) do {                                          \
        uint32_t _b = sb + (uint32_t)((g) * M5_HALF + (s) * M5_CHK);          \
        uint32_t _ao = (uint32_t)((lar * KPAD + laq * 8) * 2);                \
        cp16(_b + _ao,          &Ah[(size_t)(brow + lar) * DIM + (k) + laq * 8]); \
        cp16(_b + M5_ALO + _ao, &Al[(size_t)(brow + lar) * DIM + (k) + laq * 8]); \
        _Pragma("unroll")                                                     \
        for (int _i = 0; _i < 2; _i++) {                                      \
            int _s2 = tid + _i * 256;                                         \
            int _br = _s2 >> 3, _bq = _s2 & 7;                                \
            uint32_t _bo = (uint32_t)((_br * KPAD + _bq * 8) * 2);            \
            cp16(_b + M5_BHI + _bo, &Bh[(size_t)((k) + _br) * DIM + bcol + _bq * 8]); \
            cp16(_b + M5_BLO + _bo, &Bl[(size_t)((k) + _br) * DIM + bcol + _bq * 8]); \
        }                                                                     \
    } while (0)

    LOAD_CHUNK(0, 0, 0);
    LOAD_CHUNK(1, 0, 256);
    CP_COMMIT();

    for (int it = 0; it < 4; it++) {
        if (it + 1 < 4) {
            const int ns = (it + 1) & 1;
            const int nk = (it + 1) * 64;
            LOAD_CHUNK(0, ns, nk);
            LOAD_CHUNK(1, ns, 256 + nk);
            CP_COMMIT();
            CP_WAIT1();
        } else {
            CP_WAIT0();
        }
        __syncthreads();

        const uint32_t base = sb + (uint32_t)(kg * M5_HALF + (it & 1) * M5_CHK);

        #pragma unroll
        for (int ks = 0; ks < 4; ks++) {
            const int kk = ks * 16;
            uint32_t ah[2][4], al[2][4], bh[4], bl[4];
            #pragma unroll
            for (int mt = 0; mt < 2; mt++) {
                uint32_t ao = ((uint32_t)((mt * 16 + aRowL) * KPAD + kk + aKp)) * 2;
                ldm_x4(ah[mt][0], ah[mt][1], ah[mt][2], ah[mt][3], base + ao);
                ldm_x4(al[mt][0], al[mt][1], al[mt][2], al[mt][3], base + M5_ALO + ao);
            }
            {
                uint32_t bo = ((uint32_t)((kk + bro) * KPAD + bco)) * 2;
                ldm_x4t(bh[0], bh[1], bh[2], bh[3], base + M5_BHI + bo);
                ldm_x4t(bl[0], bl[1], bl[2], bl[3], base + M5_BLO + bo);
            }
            #pragma unroll
            for (int mt = 0; mt < 2; mt++)
                #pragma unroll
                for (int nt = 0; nt < 2; nt++) {
                    mma_bf16(acc[mt][nt], ah[mt], bh + nt * 2);
                    mma_bf16(acc[mt][nt], ah[mt], bl + nt * 2);
                    mma_bf16(acc[mt][nt], al[mt], bh + nt * 2);
                }
        }
        __syncthreads();
    }
    #undef LOAD_CHUNK

    // combine k-halves through smem (8KB at the start of dsm)
    float* red = (float*)dsm;
    const int rbase = ((wc * 32 + lane) * 4) * 4;
    if (kg == 1) {
        #pragma unroll
        for (int mt = 0; mt < 2; mt++)
            #pragma unroll
            for (int nt = 0; nt < 2; nt++)
                *(float4*)&red[rbase + (mt * 2 + nt) * 4] =
                    make_float4(acc[mt][nt][0], acc[mt][nt][1],
                                acc[mt][nt][2], acc[mt][nt][3]);
    }
    __syncthreads();
    if (kg == 0) {
        #pragma unroll
        for (int mt = 0; mt < 2; mt++)
            #pragma unroll
            for (int nt = 0; nt < 2; nt++) {
                float4 t = *(float4*)&red[rbase + (mt * 2 + nt) * 4];
                acc[mt][nt][0] += t.x;
                acc[mt][nt][1] += t.y;
                acc[mt][nt][2] += t.z;
                acc[mt][nt][3] += t.w;
            }

        const float g = (j.mode == 2) ? tanhf(ga[0]) : 0.f;
        const float omg = 1.0f - g;
        const int er0 = brow + (lane >> 2);
        const int ec0 = bcol + wc * 16 + (lane & 3) * 2;

        #pragma unroll
        for (int mt = 0; mt < 2; mt++) {
            #pragma unroll
            for (int nt = 0; nt < 2; nt++) {
                #pragma unroll
                for (int half = 0; half < 2; half++) {
                    int r = er0 + mt * 16 + half * 8;
                    int c = ec0 + nt * 8;
                    int off = r * DIM + c;
                    float v0 = acc[mt][nt][half * 2 + 0];
                    float v1 = acc[mt][nt][half * 2 + 1];
                    if (j.mode == 1) {
                        v0 += g_buf[j.addi][off];
                        v1 += g_buf[j.addi][off + 1];
                    } else if (j.mode == 2) {
                        v0 = g * (v0 + g_buf[j.addi][off])     + ((r == c)     ? omg : 0.f);
                        v1 = g * (v1 + g_buf[j.addi][off + 1]) + ((r == c + 1) ? omg : 0.f);
                    }
                    if (j.outfp >= 0) *(float2*)&g_buf[j.outfp][off] = make_float2(v0, v1);
                    if (j.outhl >= 0) split_store(j.outhl, off, v0, v1);
                    if (j.outf16) {
                        __half2 hv = __floats2half2_rn(v0, v1);
                        *(uint32_t*)&g_Hf[off] = *(uint32_t*)&hv;
                    }
                }
            }
        }
    }
}

// ======================= big GEMM: fp16, CTA 128x64, 2 CTAs/SM (R15) =======
#define MG_AS   0
#define MG_BS   36864
#define MG_TOT  55296
#define MG_ABUF 18432
#define MG_BBUF 9216

__global__ __launch_bounds__(256, 2)
void mma_gemm3(float* __restrict__ out) {
    extern __shared__ char dsm[];
    const uint32_t sb = smem_u32(dsm);

    const int tid  = threadIdx.x;
    const int wid  = tid >> 5;
    const int lane = tid & 31;
    const int wr = wid & 1;
    const int wc = wid >> 1;
    const int brow = blockIdx.x * 128;
    const int bcol = blockIdx.y * 64;

    float acc[4][2][4];
    #pragma unroll
    for (int mt = 0; mt < 4; mt++)
        #pragma unroll
        for (int nt = 0; nt < 2; nt++)
            #pragma unroll
            for (int q = 0; q < 4; q++) acc[mt][nt][q] = 0.f;

    const int aRow = wr * 64 + (lane & 15);
    const int aKp  = (lane >> 4) * 8;
    const int bRow = wc * 16 + (lane & 7);
    const int bKp  = ((lane >> 3) & 1) * 8;

    #pragma unroll
    for (int i = 0; i < 4; i++) {
        int s = tid + i * 256;
        int row = s >> 3, q = s & 7;
        cp16(sb + MG_AS + (uint32_t)((row * KPAD + q * 8) * 2),
             &g_hf[(size_t)(brow + row) * DIM + q * 8]);
    }
    #pragma unroll
    for (int i = 0; i < 2; i++) {
        int s = tid + i * 256;
        int row = s >> 3, q = s & 7;
        cp16(sb + MG_BS + (uint32_t)((row * KPAD + q * 8) * 2),
             &g_Hf[(size_t)(bcol + row) * DIM + q * 8]);
    }
    CP_COMMIT();

    for (int ch = 0; ch < 8; ch++) {
        if (ch + 1 < 8) {
            const int nb = (ch + 1) & 1;
            const int nk = (ch + 1) * 64;
            #pragma unroll
            for (int i = 0; i < 4; i++) {
                int s = tid + i * 256;
                int row = s >> 3, q = s & 7;
                cp16(sb + MG_AS + (uint32_t)(nb * MG_ABUF + (row * KPAD + q * 8) * 2),
                     &g_hf[(size_t)(brow + row) * DIM + nk + q * 8]);
            }
            #pragma unroll
            for (int i = 0; i < 2; i++) {
                int s = tid + i * 256;
                int row = s >> 3, q = s & 7;
                cp16(sb + MG_BS + (uint32_t)(nb * MG_BBUF + (row * KPAD + q * 8) * 2),
                     &g_Hf[(size_t)(bcol + row) * DIM + nk + q * 8]);
            }
            CP_COMMIT();
            CP_WAIT1();
        } else {
            CP_WAIT0();
        }
        __syncthreads();

        const uint32_t aB = sb + MG_AS + (uint32_t)((ch & 1) * MG_ABUF);
        const uint32_t bB = sb + MG_BS + (uint32_t)((ch & 1) * MG_BBUF);

        #pragma unroll
        for (int ks = 0; ks < 4; ks++) {
            const int kk = ks * 16;
            uint32_t af[4][4], bf[2][2];
            #pragma unroll
            for (int mt = 0; mt < 4; mt++) {
                uint32_t ao = ((uint32_t)((aRow + mt * 16) * KPAD + kk + aKp)) * 2;
                ldm_x4(af[mt][0], af[mt][1], af[mt][2], af[mt][3], aB + ao);
            }
            #pragma unroll
            for (int nt = 0; nt < 2; nt++) {
                uint32_t bo = ((uint32_t)((bRow + nt * 8) * KPAD + kk + bKp)) * 2;
                ldm_x2(bf[nt][0], bf[nt][1], bB + bo);
            }
            #pragma unroll
            for (int mt = 0; mt < 4; mt++)
                #pragma unroll
                for (int nt = 0; nt < 2; nt++)
                    mma_f16(acc[mt][nt], af[mt], bf[nt]);
        }
        __syncthreads();
    }

    const int er = brow + wr * 64 + (lane >> 2);
    const int ec = bcol + wc * 16 + (lane & 3) * 2;
    #pragma unroll
    for (int mt = 0; mt < 4; mt++) {
        #pragma unroll
        for (int nt = 0; nt < 2; nt++) {
            float* p0 = out + (size_t)(er + mt * 16) * DIM + ec + nt * 8;
            *(float2*)p0 = make_float2(acc[mt][nt][0], acc[mt][nt][1]);
            float* p1 = out + (size_t)(er + mt * 16 + 8) * DIM + ec + nt * 8;
            *(float2*)p1 = make_float2(acc[mt][nt][2], acc[mt][nt][3]);
        }
    }
}

// ---------------------------------------------------------------------------
extern "C" void kernel_launch(void* const* d_in, const int* in_sizes, int n_in,
                              void* d_out, int out_size) {
    const float* h  = (const float*)d_in[0];
    const float* W  = (const float*)d_in[1];
    const float* ga = (const float*)d_in[2];
    const float* p  = (const float*)d_in[3];
    float* out = (float*)d_out;

    const int R = in_sizes[0] / DIM;          // B*S = 16384

    // host-side polynomial coefficients (doubles; deterministic)
    double Ac[12] = {0}, Bc[12] = {0}, Cc[12] = {0}, Dc[12] = {0};
    Ac[0] = 1.0;
    {
        const double dt = 0.1, beta = 2.0 * sqrt(2.1), c1 = 1.0 - dt * beta;
        for (int n = 0; n < 10; n++) {
            double Cn[12], Dn[12];
            for (int k = 0; k < 12; k++) {
                Cn[k] = c1 * Cc[k] + (k > 0 ? dt * Ac[k - 1] : 0.0);
                Dn[k] = c1 * Dc[k] + (k > 0 ? dt * Bc[k - 1] : 0.0);
            }
            Dn[0] += dt;
            for (int k = 0; k < 12; k++) {
                Cc[k] = Cn[k];  Dc[k] = Dn[k];
                Ac[k] += dt * Cn[k];
                Bc[k] += dt * Dn[k];
            }
        }
    }
    Coef cf;
    for (int j = 0; j < 3; j++)
        for (int m = 0; m < 4; m++) {
            cf.P[j][m] = (float)Ac[4 * j + m];
            cf.Q[j][m] = (float)Bc[4 * j + m];
        }

    const int PAIR_BLKS = (DIM * DIM / 2 + 255) / 256;
    const int HVEC = R * DIM / 4;

    cudaFuncSetAttribute(mma512, cudaFuncAttributeMaxDynamicSharedMemorySize, M5_TOT);
    cudaFuncSetAttribute(mma_gemm3, cudaFuncAttributeMaxDynamicSharedMemorySize, MG_TOT);

    build_degN<<<DIM, 256>>>(W, p);
    split_h<<<(HVEC + 255) / 256, 256>>>(h, HVEC);

    Job jN2 = {HB_N,  HB_N,  0, 0,      BUF_N2, HB_N2, 0};
    Job jN3 = {HB_N,  HB_N2, 0, 0,      BUF_N3, -1,    0};
    Job jN4 = {HB_N2, HB_N2, 0, 0,      -1,     HB_N4, 0};
    Job jE  = {HB_N4, HB_D2, 1, BUF_D1, -1,     HB_E,  0};
    Job jH  = {HB_N4, HB_E,  2, BUF_D0, -1,     -1,    1};

    mma512<<<dim3(16, 8, 1), 256, M5_TOT>>>(jN2, jN2, ga);   // N2
    mma512<<<dim3(16, 8, 2), 256, M5_TOT>>>(jN3, jN4, ga);   // N3 + N4
    build_D<<<PAIR_BLKS, 256>>>(p, cf);
    mma512<<<dim3(16, 8, 1), 256, M5_TOT>>>(jE, jE, ga);     // E = N4*D2 + D1
    mma512<<<dim3(16, 8, 1), 256, M5_TOT>>>(jH, jH, ga);     // H (emits fp16)

    mma_gemm3<<<dim3(R / 128, DIM / 64), 256, MG_TOT>>>(out);
}

// round 17
// speedup vs baseline: 1.0465x; 1.0465x over previous
#include <cuda_runtime.h>
#include <cuda_bf16.h>
#include <cuda_fp16.h>
#include <math.h>
#include <cstdint>

// ---------------------------------------------------------------------------
// SOMI settling layer — Paterson-Stockmeyer collapsed formulation.
//   N = |W|/deg - (1.1 + p) on diag;  H = (1-g)I + g*(D0 + N^4(D1 + N^4 D2))
//   out = H @ h over the hidden dim.
// N2/N3/N4: mma.sync bf16 hi/lo 3-product (accuracy-critical, feed build_D).
// E/H:      mma.sync fp16 single-product (errors land only in H, which the
//           big GEMM already consumes at fp16; budget 1e-3, predicted ~5e-4).
// Big GEMM: mma.sync fp16 single-product, 128x64 CTA, 2 CTAs/SM (at floor).
//
// HARD RULES LEARNED:
//  R3/R4: never pass __device__ global symbols as host-side kernel args.
//  R6:    harness compiles baseline sm_100 -> no tcgen05/TMEM; mma.sync only.
//  R9:    single-buffered smem mma loops are ~90% stalled -> cp.async pipeline.
//  R11:   big GEMM hit the mma.sync compute floor -> fp16 single product.
//  R13:   16-chunk loops are barrier/ldmatrix latency-bound -> BK=64.
//  R14:   2 accumulators/warp -> MMA RAW chain bound -> 4 accs.
//  R15/16: chain launches have ~6-9us fixed floor; tile tuning is exhausted ->
//          reduce work via fp16 where the error budget allows.
// ---------------------------------------------------------------------------

#define DIM 512
#define RMAX (4 * 4096)

// fp32 arena ids
#define BUF_N   0
#define BUF_N2  1
#define BUF_N3  2
#define BUF_D0  3
#define BUF_D1  4
// bf16 hi/lo arena ids
#define HB_N    0
#define HB_N2   1
// fp16 arena ids
#define F_N4    0
#define F_D2    1
#define F_E     2
#define F_HOUT  3   // sentinel: write g_Hf

__device__ __align__(16) float g_buf[5][DIM * DIM];
__device__ __align__(16) __nv_bfloat16 g_bhi[2][DIM * DIM];
__device__ __align__(16) __nv_bfloat16 g_blo[2][DIM * DIM];
__device__ __align__(16) __half g_f16[3][DIM * DIM];  // N4, D2, E in fp16
__device__ __align__(16) __half g_Hf[DIM * DIM];      // H in fp16 (big GEMM B)
__device__ __align__(16) __half g_hf[RMAX * DIM];     // h in fp16 (big GEMM A)

struct Coef { float P[3][4]; float Q[3][4]; };
struct Job  { int ahl, bhl, mode, addi, outfp, outhl, outf16; };
struct JobH { int af, bf, mode, addi, outf16; };

// ======================= helpers ===========================================
__device__ __forceinline__ uint32_t smem_u32(const void* p) {
    uint32_t a;
    asm("{ .reg .u64 t; cvta.to.shared.u64 t, %1; cvt.u32.u64 %0, t; }"
        : "=r"(a) : "l"(p));
    return a;
}
__device__ __forceinline__ uint32_t bf2_pack(__nv_bfloat16 a, __nv_bfloat16 b) {
    __nv_bfloat162 t = __halves2bfloat162(a, b);
    return *reinterpret_cast<uint32_t*>(&t);
}
__device__ __forceinline__ void cp16(uint32_t dst, const void* src) {
    asm volatile("cp.async.cg.shared.global [%0], [%1], 16;"
                 :: "r"(dst), "l"(src) : "memory");
}
#define CP_COMMIT() asm volatile("cp.async.commit_group;" ::: "memory")
#define CP_WAIT1()  asm volatile("cp.async.wait_group 1;" ::: "memory")
#define CP_WAIT0()  asm volatile("cp.async.wait_group 0;" ::: "memory")

__device__ __forceinline__ void ldm_x4(uint32_t& r0, uint32_t& r1,
                                       uint32_t& r2, uint32_t& r3, uint32_t a) {
    asm volatile("ldmatrix.sync.aligned.m8n8.x4.shared.b16 {%0,%1,%2,%3}, [%4];"
                 : "=r"(r0), "=r"(r1), "=r"(r2), "=r"(r3) : "r"(a));
}
__device__ __forceinline__ void ldm_x2(uint32_t& r0, uint32_t& r1, uint32_t a) {
    asm volatile("ldmatrix.sync.aligned.m8n8.x2.shared.b16 {%0,%1}, [%2];"
                 : "=r"(r0), "=r"(r1) : "r"(a));
}
__device__ __forceinline__ void ldm_x4t(uint32_t& r0, uint32_t& r1,
                                        uint32_t& r2, uint32_t& r3, uint32_t a) {
    asm volatile("ldmatrix.sync.aligned.m8n8.x4.trans.shared.b16 {%0,%1,%2,%3}, [%4];"
                 : "=r"(r0), "=r"(r1), "=r"(r2), "=r"(r3) : "r"(a));
}
__device__ __forceinline__ void mma_bf16(float* c, const uint32_t* a,
                                         const uint32_t* b) {
    asm volatile(
        "mma.sync.aligned.m16n8k16.row.col.f32.bf16.bf16.f32 "
        "{%0,%1,%2,%3}, {%4,%5,%6,%7}, {%8,%9}, {%0,%1,%2,%3};"
        : "+f"(c[0]), "+f"(c[1]), "+f"(c[2]), "+f"(c[3])
        : "r"(a[0]), "r"(a[1]), "r"(a[2]), "r"(a[3]), "r"(b[0]), "r"(b[1]));
}
__device__ __forceinline__ void mma_f16(float* c, const uint32_t* a,
                                        const uint32_t* b) {
    asm volatile(
        "mma.sync.aligned.m16n8k16.row.col.f32.f16.f16.f32 "
        "{%0,%1,%2,%3}, {%4,%5,%6,%7}, {%8,%9}, {%0,%1,%2,%3};"
        : "+f"(c[0]), "+f"(c[1]), "+f"(c[2]), "+f"(c[3])
        : "r"(a[0]), "r"(a[1]), "r"(a[2]), "r"(a[3]), "r"(b[0]), "r"(b[1]));
}
__device__ __forceinline__ void split_store(int hl, int off, float v0, float v1) {
    __nv_bfloat16 h0 = __float2bfloat16_rn(v0);
    __nv_bfloat16 h1 = __float2bfloat16_rn(v1);
    __nv_bfloat16 l0 = __float2bfloat16_rn(v0 - __bfloat162float(h0));
    __nv_bfloat16 l1 = __float2bfloat16_rn(v1 - __bfloat162float(h1));
    *(uint32_t*)&g_bhi[hl][off] = bf2_pack(h0, h1);
    *(uint32_t*)&g_blo[hl][off] = bf2_pack(l0, l1);
}
__device__ __forceinline__ void f16_store(__half* dst, int off, float v0, float v1) {
    __half2 hv = __floats2half2_rn(v0, v1);
    *(uint32_t*)&dst[off] = *(uint32_t*)&hv;
}

// ======================= build kernels =====================================
__global__ __launch_bounds__(256)
void build_degN(const float* __restrict__ W, const float* __restrict__ p) {
    __shared__ float red[8];
    const int e   = blockIdx.x;
    const int tid = threadIdx.x;
    const float* row = W + (size_t)e * DIM;

    float s = fabsf(row[tid]) + fabsf(row[tid + 256]);
    #pragma unroll
    for (int o = 16; o > 0; o >>= 1) s += __shfl_down_sync(0xffffffffu, s, o);
    if ((tid & 31) == 0) red[tid >> 5] = s;
    __syncthreads();
    if (tid == 0) {
        float t = 0.f;
        #pragma unroll
        for (int w = 0; w < 8; w++) t += red[w];
        red[0] = fmaxf(t, 1e-8f);
    }
    __syncthreads();
    const float dg = red[0];

    int d = tid * 2;
    int idx = e * DIM + d;
    float m0 = fabsf(row[d])     / dg;
    float m1 = fabsf(row[d + 1]) / dg;
    if (e == d)     m0 -= (1.1f + p[d]);
    if (e == d + 1) m1 -= (1.1f + p[d + 1]);
    g_buf[BUF_N][idx]     = m0;
    g_buf[BUF_N][idx + 1] = m1;
    split_store(HB_N, idx, m0, m1);
}

__global__ void split_h(const float* __restrict__ h, int nvec) {
    int v = blockIdx.x * blockDim.x + threadIdx.x;
    if (v >= nvec) return;
    float4 x = ((const float4*)h)[v];
    int idx = v * 4;
    __half2 a = __floats2half2_rn(x.x, x.y);
    __half2 b = __floats2half2_rn(x.z, x.w);
    *(uint2*)&g_hf[idx] = make_uint2(*(uint32_t*)&a, *(uint32_t*)&b);
}

__global__ __launch_bounds__(256)
void build_D(const float* __restrict__ p, Coef cf) {
    int v = blockIdx.x * blockDim.x + threadIdx.x;
    if (v >= DIM * DIM / 2) return;
    int idx = v * 2;
    int e = idx >> 9;
    int d = idx & (DIM - 1);
    float r[3][2];
    #pragma unroll
    for (int u = 0; u < 2; u++) {
        int dd = d + u;
        float x0 = (e == dd) ? 1.f : 0.f;
        float x1 = g_buf[BUF_N ][idx + u];
        float x2 = g_buf[BUF_N2][idx + u];
        float x3 = g_buf[BUF_N3][idx + u];
        float pd = p[dd];
        #pragma unroll
        for (int j = 0; j < 3; j++) {
            float vp = cf.P[j][0] * x0 + cf.P[j][1] * x1 + cf.P[j][2] * x2 + cf.P[j][3] * x3;
            float vq = cf.Q[j][0] * x0 + cf.Q[j][1] * x1 + cf.Q[j][2] * x2 + cf.Q[j][3] * x3;
            r[j][u] = vp + vq * pd;
        }
    }
    g_buf[BUF_D0][idx]     = r[0][0];
    g_buf[BUF_D0][idx + 1] = r[0][1];
    g_buf[BUF_D1][idx]     = r[1][0];
    g_buf[BUF_D1][idx + 1] = r[1][1];
    f16_store(g_f16[F_D2], idx, r[2][0], r[2][1]);
}

// ======================= bf16 3-product 512^3 GEMM (warp split-K) ==========
// C = A(hi/lo) @ B(hi/lo); CTA 32x64, grid (16,8,z), 256 threads / 8 warps.
// kg = wid>>2 selects k-half; wc = wid&3 selects 16-col quarter.
// Smem: 4 chunk blocks (2 halves x 2 stages), 27648 B each = 110592 B.
#define M5_CHK  27648
#define M5_HALF 55296
#define M5_ALO  4608
#define M5_BHI  9216
#define M5_BLO  18432
#define M5_TOT  110592
#define KPAD 72

__global__ __launch_bounds__(256, 1)
void mma512(Job j0, Job j1, const float* __restrict__ ga) {
    extern __shared__ char dsm[];
    const uint32_t sb = smem_u32(dsm);

    const Job j = (blockIdx.z == 0) ? j0 : j1;
    const int tid  = threadIdx.x;
    const int wid  = tid >> 5;
    const int lane = tid & 31;
    const int kg   = wid >> 2;
    const int wc   = wid & 3;
    const int brow = blockIdx.x * 32;
    const int bcol = blockIdx.y * 64;

    const __nv_bfloat16* __restrict__ Ah = g_bhi[j.ahl];
    const __nv_bfloat16* __restrict__ Al = g_blo[j.ahl];
    const __nv_bfloat16* __restrict__ Bh = g_bhi[j.bhl];
    const __nv_bfloat16* __restrict__ Bl = g_blo[j.bhl];

    float acc[2][2][4];
    #pragma unroll
    for (int mt = 0; mt < 2; mt++)
        #pragma unroll
        for (int nt = 0; nt < 2; nt++)
            #pragma unroll
            for (int q = 0; q < 4; q++) acc[mt][nt][q] = 0.f;

    const int aRowL = lane & 15;
    const int aKp   = (lane >> 4) * 8;
    const int bg    = lane >> 3;
    const int bro   = (bg & 1) * 8 + (lane & 7);
    const int bco   = wc * 16 + (bg >> 1) * 8;
    const int lar = tid >> 3, laq = tid & 7;

    #define LOAD_CHUNK(g, s, k) do {                                          \
        uint32_t _b = sb + (uint32_t)((g) * M5_HALF + (s) * M5_CHK);          \
        uint32_t _ao = (uint32_t)((lar * KPAD + laq * 8) * 2);                \
        cp16(_b + _ao,          &Ah[(size_t)(brow + lar) * DIM + (k) + laq * 8]); \
        cp16(_b + M5_ALO + _ao, &Al[(size_t)(brow + lar) * DIM + (k) + laq * 8]); \
        _Pragma("unroll")                                                     \
        for (int _i = 0; _i < 2; _i++) {                                      \
            int _s2 = tid + _i * 256;                                         \
            int _br = _s2 >> 3, _bq = _s2 & 7;                                \
            uint32_t _bo = (uint32_t)((_br * KPAD + _bq * 8) * 2);            \
            cp16(_b + M5_BHI + _bo, &Bh[(size_t)((k) + _br) * DIM + bcol + _bq * 8]); \
            cp16(_b + M5_BLO + _bo, &Bl[(size_t)((k) + _br) * DIM + bcol + _bq * 8]); \
        }                                                                     \
    } while (0)

    LOAD_CHUNK(0, 0, 0);
    LOAD_CHUNK(1, 0, 256);
    CP_COMMIT();

    for (int it = 0; it < 4; it++) {
        if (it + 1 < 4) {
            const int ns = (it + 1) & 1;
            const int nk = (it + 1) * 64;
            LOAD_CHUNK(0, ns, nk);
            LOAD_CHUNK(1, ns, 256 + nk);
            CP_COMMIT();
            CP_WAIT1();
        } else {
            CP_WAIT0();
        }
        __syncthreads();

        const uint32_t base = sb + (uint32_t)(kg * M5_HALF + (it & 1) * M5_CHK);

        #pragma unroll
        for (int ks = 0; ks < 4; ks++) {
            const int kk = ks * 16;
            uint32_t ah[2][4], al[2][4], bh[4], bl[4];
            #pragma unroll
            for (int mt = 0; mt < 2; mt++) {
                uint32_t ao = ((uint32_t)((mt * 16 + aRowL) * KPAD + kk + aKp)) * 2;
                ldm_x4(ah[mt][0], ah[mt][1], ah[mt][2], ah[mt][3], base + ao);
                ldm_x4(al[mt][0], al[mt][1], al[mt][2], al[mt][3], base + M5_ALO + ao);
            }
            {
                uint32_t bo = ((uint32_t)((kk + bro) * KPAD + bco)) * 2;
                ldm_x4t(bh[0], bh[1], bh[2], bh[3], base + M5_BHI + bo);
                ldm_x4t(bl[0], bl[1], bl[2], bl[3], base + M5_BLO + bo);
            }
            #pragma unroll
            for (int mt = 0; mt < 2; mt++)
                #pragma unroll
                for (int nt = 0; nt < 2; nt++) {
                    mma_bf16(acc[mt][nt], ah[mt], bh + nt * 2);
                    mma_bf16(acc[mt][nt], ah[mt], bl + nt * 2);
                    mma_bf16(acc[mt][nt], al[mt], bh + nt * 2);
                }
        }
        __syncthreads();
    }
    #undef LOAD_CHUNK

    float* red = (float*)dsm;
    const int rbase = ((wc * 32 + lane) * 4) * 4;
    if (kg == 1) {
        #pragma unroll
        for (int mt = 0; mt < 2; mt++)
            #pragma unroll
            for (int nt = 0; nt < 2; nt++)
                *(float4*)&red[rbase + (mt * 2 + nt) * 4] =
                    make_float4(acc[mt][nt][0], acc[mt][nt][1],
                                acc[mt][nt][2], acc[mt][nt][3]);
    }
    __syncthreads();
    if (kg == 0) {
        #pragma unroll
        for (int mt = 0; mt < 2; mt++)
            #pragma unroll
            for (int nt = 0; nt < 2; nt++) {
                float4 t = *(float4*)&red[rbase + (mt * 2 + nt) * 4];
                acc[mt][nt][0] += t.x;
                acc[mt][nt][1] += t.y;
                acc[mt][nt][2] += t.z;
                acc[mt][nt][3] += t.w;
            }

        const int er0 = brow + (lane >> 2);
        const int ec0 = bcol + wc * 16 + (lane & 3) * 2;

        #pragma unroll
        for (int mt = 0; mt < 2; mt++) {
            #pragma unroll
            for (int nt = 0; nt < 2; nt++) {
                #pragma unroll
                for (int half = 0; half < 2; half++) {
                    int r = er0 + mt * 16 + half * 8;
                    int c = ec0 + nt * 8;
                    int off = r * DIM + c;
                    float v0 = acc[mt][nt][half * 2 + 0];
                    float v1 = acc[mt][nt][half * 2 + 1];
                    if (j.outfp >= 0) *(float2*)&g_buf[j.outfp][off] = make_float2(v0, v1);
                    if (j.outhl >= 0) split_store(j.outhl, off, v0, v1);
                    if (j.outf16 >= 0) f16_store(g_f16[j.outf16], off, v0, v1);
                }
            }
        }
    }
}

// ======================= fp16 single-product 512^3 GEMM ====================
// C = A @ B (both fp16 from g_f16); same warp-split-K skeleton, half smem.
// mode 1: C += g_buf[addi] -> g_f16[out];  mode 2: g*(C+g_buf[addi])+(1-g)I
// -> g_Hf. Smem: 4 blocks x 13824 B = 55296 B; block: A@0 (4608), B@4608.
#define MH_CHK  13824
#define MH_HALF 27648
#define MH_B    4608
#define MH_TOT  55296

__global__ __launch_bounds__(256, 1)
void mma512h(JobH j, const float* __restrict__ ga) {
    extern __shared__ char dsm[];
    const uint32_t sb = smem_u32(dsm);

    const int tid  = threadIdx.x;
    const int wid  = tid >> 5;
    const int lane = tid & 31;
    const int kg   = wid >> 2;
    const int wc   = wid & 3;
    const int brow = blockIdx.x * 32;
    const int bcol = blockIdx.y * 64;

    const __half* __restrict__ Af = g_f16[j.af];
    const __half* __restrict__ Bf = g_f16[j.bf];

    float acc[2][2][4];
    #pragma unroll
    for (int mt = 0; mt < 2; mt++)
        #pragma unroll
        for (int nt = 0; nt < 2; nt++)
            #pragma unroll
            for (int q = 0; q < 4; q++) acc[mt][nt][q] = 0.f;

    const int aRowL = lane & 15;
    const int aKp   = (lane >> 4) * 8;
    const int bg    = lane >> 3;
    const int bro   = (bg & 1) * 8 + (lane & 7);
    const int bco   = wc * 16 + (bg >> 1) * 8;
    const int lar = tid >> 3, laq = tid & 7;

    #define LOAD_CHUNK_H(g, s, k) do {                                        \
        uint32_t _b = sb + (uint32_t)((g) * MH_HALF + (s) * MH_CHK);          \
        cp16(_b + (uint32_t)((lar * KPAD + laq * 8) * 2),                     \
             &Af[(size_t)(brow + lar) * DIM + (k) + laq * 8]);                \
        _Pragma("unroll")                                                     \
        for (int _i = 0; _i < 2; _i++) {                                      \
            int _s2 = tid + _i * 256;                                         \
            int _br = _s2 >> 3, _bq = _s2 & 7;                                \
            cp16(_b + MH_B + (uint32_t)((_br * KPAD + _bq * 8) * 2),          \
                 &Bf[(size_t)((k) + _br) * DIM + bcol + _bq * 8]);            \
        }                                                                     \
    } while (0)

    LOAD_CHUNK_H(0, 0, 0);
    LOAD_CHUNK_H(1, 0, 256);
    CP_COMMIT();

    for (int it = 0; it < 4; it++) {
        if (it + 1 < 4) {
            const int ns = (it + 1) & 1;
            const int nk = (it + 1) * 64;
            LOAD_CHUNK_H(0, ns, nk);
            LOAD_CHUNK_H(1, ns, 256 + nk);
            CP_COMMIT();
            CP_WAIT1();
        } else {
            CP_WAIT0();
        }
        __syncthreads();

        const uint32_t base = sb + (uint32_t)(kg * MH_HALF + (it & 1) * MH_CHK);

        #pragma unroll
        for (int ks = 0; ks < 4; ks++) {
            const int kk = ks * 16;
            uint32_t af[2][4], bf[4];
            #pragma unroll
            for (int mt = 0; mt < 2; mt++) {
                uint32_t ao = ((uint32_t)((mt * 16 + aRowL) * KPAD + kk + aKp)) * 2;
                ldm_x4(af[mt][0], af[mt][1], af[mt][2], af[mt][3], base + ao);
            }
            {
                uint32_t bo = ((uint32_t)((kk + bro) * KPAD + bco)) * 2;
                ldm_x4t(bf[0], bf[1], bf[2], bf[3], base + MH_B + bo);
            }
            #pragma unroll
            for (int mt = 0; mt < 2; mt++)
                #pragma unroll
                for (int nt = 0; nt < 2; nt++)
                    mma_f16(acc[mt][nt], af[mt], bf + nt * 2);
        }
        __syncthreads();
    }
    #undef LOAD_CHUNK_H

    float* red = (float*)dsm;
    const int rbase = ((wc * 32 + lane) * 4) * 4;
    if (kg == 1) {
        #pragma unroll
        for (int mt = 0; mt < 2; mt++)
            #pragma unroll
            for (int nt = 0; nt < 2; nt++)
                *(float4*)&red[rbase + (mt * 2 + nt) * 4] =
                    make_float4(acc[mt][nt][0], acc[mt][nt][1],
                                acc[mt][nt][2], acc[mt][nt][3]);
    }
    __syncthreads();
    if (kg == 0) {
        #pragma unroll
        for (int mt = 0; mt < 2; mt++)
            #pragma unroll
            for (int nt = 0; nt < 2; nt++) {
                float4 t = *(float4*)&red[rbase + (mt * 2 + nt) * 4];
                acc[mt][nt][0] += t.x;
                acc[mt][nt][1] += t.y;
                acc[mt][nt][2] += t.z;
                acc[mt][nt][3] += t.w;
            }

        const float g = (j.mode == 2) ? tanhf(ga[0]) : 0.f;
        const float omg = 1.0f - g;
        const int er0 = brow + (lane >> 2);
        const int ec0 = bcol + wc * 16 + (lane & 3) * 2;

        #pragma unroll
        for (int mt = 0; mt < 2; mt++) {
            #pragma unroll
            for (int nt = 0; nt < 2; nt++) {
                #pragma unroll
                for (int half = 0; half < 2; half++) {
                    int r = er0 + mt * 16 + half * 8;
                    int c = ec0 + nt * 8;
                    int off = r * DIM + c;
                    float v0 = acc[mt][nt][half * 2 + 0] + g_buf[j.addi][off];
                    float v1 = acc[mt][nt][half * 2 + 1] + g_buf[j.addi][off + 1];
                    if (j.mode == 2) {
                        v0 = g * v0 + ((r == c)     ? omg : 0.f);
                        v1 = g * v1 + ((r == c + 1) ? omg : 0.f);
                    }
                    if (j.outf16 == F_HOUT) f16_store(g_Hf, off, v0, v1);
                    else                    f16_store(g_f16[j.outf16], off, v0, v1);
                }
            }
        }
    }
}

// ======================= big GEMM: fp16, CTA 128x64, 2 CTAs/SM =============
#define MG_AS   0
#define MG_BS   36864
#define MG_TOT  55296
#define MG_ABUF 18432
#define MG_BBUF 9216

__global__ __launch_bounds__(256, 2)
void mma_gemm3(float* __restrict__ out) {
    extern __shared__ char dsm[];
    const uint32_t sb = smem_u32(dsm);

    const int tid  = threadIdx.x;
    const int wid  = tid >> 5;
    const int lane = tid & 31;
    const int wr = wid & 1;
    const int wc = wid >> 1;
    const int brow = blockIdx.x * 128;
    const int bcol = blockIdx.y * 64;

    float acc[4][2][4];
    #pragma unroll
    for (int mt = 0; mt < 4; mt++)
        #pragma unroll
        for (int nt = 0; nt < 2; nt++)
            #pragma unroll
            for (int q = 0; q < 4; q++) acc[mt][nt][q] = 0.f;

    const int aRow = wr * 64 + (lane & 15);
    const int aKp  = (lane >> 4) * 8;
    const int bRow = wc * 16 + (lane & 7);
    const int bKp  = ((lane >> 3) & 1) * 8;

    #pragma unroll
    for (int i = 0; i < 4; i++) {
        int s = tid + i * 256;
        int row = s >> 3, q = s & 7;
        cp16(sb + MG_AS + (uint32_t)((row * KPAD + q * 8) * 2),
             &g_hf[(size_t)(brow + row) * DIM + q * 8]);
    }
    #pragma unroll
    for (int i = 0; i < 2; i++) {
        int s = tid + i * 256;
        int row = s >> 3, q = s & 7;
        cp16(sb + MG_BS + (uint32_t)((row * KPAD + q * 8) * 2),
             &g_Hf[(size_t)(bcol + row) * DIM + q * 8]);
    }
    CP_COMMIT();

    for (int ch = 0; ch < 8; ch++) {
        if (ch + 1 < 8) {
            const int nb = (ch + 1) & 1;
            const int nk = (ch + 1) * 64;
            #pragma unroll
            for (int i = 0; i < 4; i++) {
                int s = tid + i * 256;
                int row = s >> 3, q = s & 7;
                cp16(sb + MG_AS + (uint32_t)(nb * MG_ABUF + (row * KPAD + q * 8) * 2),
                     &g_hf[(size_t)(brow + row) * DIM + nk + q * 8]);
            }
            #pragma unroll
            for (int i = 0; i < 2; i++) {
                int s = tid + i * 256;
                int row = s >> 3, q = s & 7;
                cp16(sb + MG_BS + (uint32_t)(nb * MG_BBUF + (row * KPAD + q * 8) * 2),
                     &g_Hf[(size_t)(bcol + row) * DIM + nk + q * 8]);
            }
            CP_COMMIT();
            CP_WAIT1();
        } else {
            CP_WAIT0();
        }
        __syncthreads();

        const uint32_t aB = sb + MG_AS + (uint32_t)((ch & 1) * MG_ABUF);
        const uint32_t bB = sb + MG_BS + (uint32_t)((ch & 1) * MG_BBUF);

        #pragma unroll
        for (int ks = 0; ks < 4; ks++) {
            const int kk = ks * 16;
            uint32_t af[4][4], bf[2][2];
            #pragma unroll
            for (int mt = 0; mt < 4; mt++) {
                uint32_t ao = ((uint32_t)((aRow + mt * 16) * KPAD + kk + aKp)) * 2;
                ldm_x4(af[mt][0], af[mt][1], af[mt][2], af[mt][3], aB + ao);
            }
            #pragma unroll
            for (int nt = 0; nt < 2; nt++) {
                uint32_t bo = ((uint32_t)((bRow + nt * 8) * KPAD + kk + bKp)) * 2;
                ldm_x2(bf[nt][0], bf[nt][1], bB + bo);
            }
            #pragma unroll
            for (int mt = 0; mt < 4; mt++)
                #pragma unroll
                for (int nt = 0; nt < 2; nt++)
                    mma_f16(acc[mt][nt], af[mt], bf[nt]);
        }
        __syncthreads();
    }

    const int er = brow + wr * 64 + (lane >> 2);
    const int ec = bcol + wc * 16 + (lane & 3) * 2;
    #pragma unroll
    for (int mt = 0; mt < 4; mt++) {
        #pragma unroll
        for (int nt = 0; nt < 2; nt++) {
            float* p0 = out + (size_t)(er + mt * 16) * DIM + ec + nt * 8;
            *(float2*)p0 = make_float2(acc[mt][nt][0], acc[mt][nt][1]);
            float* p1 = out + (size_t)(er + mt * 16 + 8) * DIM + ec + nt * 8;
            *(float2*)p1 = make_float2(acc[mt][nt][2], acc[mt][nt][3]);
        }
    }
}

// ---------------------------------------------------------------------------
extern "C" void kernel_launch(void* const* d_in, const int* in_sizes, int n_in,
                              void* d_out, int out_size) {
    const float* h  = (const float*)d_in[0];
    const float* W  = (const float*)d_in[1];
    const float* ga = (const float*)d_in[2];
    const float* p  = (const float*)d_in[3];
    float* out = (float*)d_out;

    const int R = in_sizes[0] / DIM;          // B*S = 16384

    // host-side polynomial coefficients (doubles; deterministic)
    double Ac[12] = {0}, Bc[12] = {0}, Cc[12] = {0}, Dc[12] = {0};
    Ac[0] = 1.0;
    {
        const double dt = 0.1, beta = 2.0 * sqrt(2.1), c1 = 1.0 - dt * beta;
        for (int n = 0; n < 10; n++) {
            double Cn[12], Dn[12];
            for (int k = 0; k < 12; k++) {
                Cn[k] = c1 * Cc[k] + (k > 0 ? dt * Ac[k - 1] : 0.0);
                Dn[k] = c1 * Dc[k] + (k > 0 ? dt * Bc[k - 1] : 0.0);
            }
            Dn[0] += dt;
            for (int k = 0; k < 12; k++) {
                Cc[k] = Cn[k];  Dc[k] = Dn[k];
                Ac[k] += dt * Cn[k];
                Bc[k] += dt * Dn[k];
            }
        }
    }
    Coef cf;
    for (int j = 0; j < 3; j++)
        for (int m = 0; m < 4; m++) {
            cf.P[j][m] = (float)Ac[4 * j + m];
            cf.Q[j][m] = (float)Bc[4 * j + m];
        }

    const int PAIR_BLKS = (DIM * DIM / 2 + 255) / 256;
    const int HVEC = R * DIM / 4;

    cudaFuncSetAttribute(mma512, cudaFuncAttributeMaxDynamicSharedMemorySize, M5_TOT);
    cudaFuncSetAttribute(mma512h, cudaFuncAttributeMaxDynamicSharedMemorySize, MH_TOT);
    cudaFuncSetAttribute(mma_gemm3, cudaFuncAttributeMaxDynamicSharedMemorySize, MG_TOT);

    build_degN<<<DIM, 256>>>(W, p);
    split_h<<<(HVEC + 255) / 256, 256>>>(h, HVEC);

    Job jN2 = {HB_N,  HB_N,  0, 0, BUF_N2, HB_N2, -1};
    Job jN3 = {HB_N,  HB_N2, 0, 0, BUF_N3, -1,    -1};
    Job jN4 = {HB_N2, HB_N2, 0, 0, -1,     -1,    F_N4};
    JobH jE = {F_N4, F_D2, 1, BUF_D1, F_E};
    JobH jH = {F_N4, F_E,  2, BUF_D0, F_HOUT};

    mma512<<<dim3(16, 8, 1), 256, M5_TOT>>>(jN2, jN2, ga);   // N2 (bf16 3-prod)
    mma512<<<dim3(16, 8, 2), 256, M5_TOT>>>(jN3, jN4, ga);   // N3 + N4
    build_D<<<PAIR_BLKS, 256>>>(p, cf);
    mma512h<<<dim3(16, 8), 256, MH_TOT>>>(jE, ga);           // E (fp16 1-prod)
    mma512h<<<dim3(16, 8), 256, MH_TOT>>>(jH, ga);           // H (fp16 1-prod)

    mma_gemm3<<<dim3(R / 128, DIM / 64), 256, MG_TOT>>>(out);
}